// round 13
// baseline (speedup 1.0000x reference)
#include <cuda_runtime.h>
#include <cuda_bf16.h>
#include <stdint.h>

#define N_NODES 50000
#define N_EDGES 200000
#define HID 32
#define M_TILES 391          // ceil(50000/128)
#define EGB 6250             // edge kernel blocks (4 edges/warp)

// ---------------- device scratch (static allocation only) ----------------
__device__ int            g_src[N_EDGES], g_dst[N_EDGES];
__device__ float          g_hA[N_NODES * HID];
__device__ float          g_hB[N_NODES * HID];
__device__ unsigned short g_w2tb[3 * 1056 * 32];       // bf16 [L][col][h]
__device__ unsigned       g_Yt[(size_t)N_NODES * 512]; // bf16x2 packed [n][o][k/2]
__device__ float          g_Yb[N_NODES * HID];         // bias image row (fp32)
__device__ float          g_agg[N_NODES * HID];
__device__ float          g_cnt[N_NODES];

// ---------------- fused pre: detect dtype + normalize + dst counts ----------
__global__ __launch_bounds__(256) void pre_kernel(const void* ei,
                                                  float* __restrict__ cnt) {
    __shared__ int any;
    if (threadIdx.x == 0) any = 0;
    __syncthreads();
    const unsigned* u = (const unsigned*)ei;
    int local = 0;
    for (int i = threadIdx.x; i < 2048; i += 256)
        if (u[2 * i + 1] != 0u) local = 1;
    if (local) atomicOr(&any, 1);
    __syncthreads();
    int is64 = (any == 0);

    int e = blockIdx.x * 256 + threadIdx.x;
    if (e >= N_EDGES) return;
    int s, d;
    if (is64) {
        const long long* p = (const long long*)ei;
        s = (int)p[e];
        d = (int)p[N_EDGES + e];
    } else {
        const int* p = (const int*)ei;
        s = p[e];
        d = p[N_EDGES + e];
    }
    s = min(max(s, 0), N_NODES - 1);
    d = min(max(d, 0), N_NODES - 1);
    g_src[e] = s;
    g_dst[e] = d;
    atomicAdd(&cnt[d], 1.f);
}

// ---------------- h0 = relu(x @ Win + b) ------------------------------------
__global__ __launch_bounds__(256) void inproj_kernel(
    const float* __restrict__ x, const float* __restrict__ W,
    const float* __restrict__ b, float* __restrict__ hout) {
    __shared__ float sW[64 * 32];
    __shared__ float sb[32];
    int tid = threadIdx.x;
    for (int i = tid; i < 64 * 32; i += 256) sW[i] = W[i];
    if (tid < 32) sb[tid] = b[tid];
    __syncthreads();
    int lane = tid & 31, wid = tid >> 5;
    int n = blockIdx.x * 8 + wid;
    if (n >= N_NODES) return;
    float xa = x[n * 64 + lane];
    float xb = x[n * 64 + 32 + lane];
    float r = sb[lane];
#pragma unroll
    for (int k = 0; k < 32; k++)
        r = fmaf(__shfl_sync(0xffffffffu, xa, k), sW[k * 32 + lane], r);
#pragma unroll
    for (int k = 0; k < 32; k++)
        r = fmaf(__shfl_sync(0xffffffffu, xb, k), sW[(k + 32) * 32 + lane], r);
    hout[n * 32 + lane] = fmaxf(r, 0.f);
}

// ---------------- w2 repack (all 3 layers, one launch) ----------------------
__global__ __launch_bounds__(256) void w2tb_all_kernel(
    const float* __restrict__ edge_w2, const float* __restrict__ edge_b2) {
    int idx = blockIdx.x * 256 + threadIdx.x;
    if (idx >= 3 * 33792) return;
    int L = idx / 33792;
    int rem = idx - L * 33792;
    int col = rem >> 5, hh = rem & 31;
    const float* w2 = edge_w2 + L * 32768;
    const float* b2 = edge_b2 + L * 1024;
    float v;
    if (col < 1024) {
        int o = col >> 5, k = col & 31;
        v = w2[k * 1024 + hh * 32 + o];
    } else {
        v = b2[hh * 32 + (col - 1024)];
    }
    __nv_bfloat16 bv = __float2bfloat16(v);
    g_w2tb[idx] = *reinterpret_cast<unsigned short*>(&bv);
}

// ---------------- Y via mma.sync bf16 HMMA ----------------------------------
__device__ __forceinline__ void hmma16816(float* c, uint32_t a0, uint32_t a1,
                                          uint32_t a2, uint32_t a3,
                                          uint32_t b0, uint32_t b1) {
    asm volatile(
        "mma.sync.aligned.m16n8k16.row.col.f32.bf16.bf16.f32 "
        "{%0,%1,%2,%3}, {%4,%5,%6,%7}, {%8,%9}, {%0,%1,%2,%3};"
        : "+f"(c[0]), "+f"(c[1]), "+f"(c[2]), "+f"(c[3])
        : "r"(a0), "r"(a1), "r"(a2), "r"(a3), "r"(b0), "r"(b1));
}

#define ASTR 36
#define BSTR 36
#define SROW 20   // stage row stride in u32 (80B: 16B-aligned, conflict-free)

// grid (391, 11): 128 rows x 96 cols per block (12 n8-tiles, 3 groups of 4).
// Epilogue stages packed pairs in smem, then 64B-contiguous uint4 row stores.
__global__ __launch_bounds__(256) void y_hmma_kernel(
    const float* __restrict__ h, const unsigned short* __restrict__ w2tb) {
    __shared__ __nv_bfloat16 sA[128 * ASTR];
    __shared__ __nv_bfloat16 sB[96 * BSTR];
    __shared__ unsigned sStage[8 * 16 * SROW];  // per-warp 16 rows x 16 u32 (+pad)
    int tid = threadIdx.x, lane = tid & 31, wid = tid >> 5;
    int m0 = blockIdx.x * 128;
    int y = blockIdx.y;
    int nb0 = y * 96;

    for (int idx = tid; idx < 128 * 32; idx += 256) {
        int r = idx >> 5, k = idx & 31;
        int n = m0 + r;
        float v = (n < N_NODES) ? __ldg(h + (size_t)n * 32 + k) : 0.f;
        sA[r * ASTR + k] = __float2bfloat16(v);
    }
    for (int idx = tid; idx < 96 * 32; idx += 256) {
        int r = idx >> 5, k = idx & 31;
        unsigned short us = w2tb[(nb0 + r) * 32 + k];
        sB[r * BSTR + k] = *reinterpret_cast<__nv_bfloat16*>(&us);
    }
    __syncthreads();

    int r = wid * 16 + (lane >> 2);
    int kc = (lane & 3) * 2;
    uint32_t A0[2], A1[2], A2[2], A3[2];
#pragma unroll
    for (int ch = 0; ch < 2; ch++) {
        int kb = ch * 16 + kc;
        A0[ch] = *reinterpret_cast<const uint32_t*>(sA + r * ASTR + kb);
        A1[ch] = *reinterpret_cast<const uint32_t*>(sA + (r + 8) * ASTR + kb);
        A2[ch] = *reinterpret_cast<const uint32_t*>(sA + r * ASTR + kb + 8);
        A3[ch] = *reinterpret_cast<const uint32_t*>(sA + (r + 8) * ASTR + kb + 8);
    }

    int n_row0 = m0 + r;
    int n_row1 = n_row0 + 8;
    int nloc_base = lane >> 2;
    unsigned* wstage = sStage + wid * 16 * SROW;
    int row = lane >> 2;       // 0..7
    int kci = lane & 3;        // 0..3

    for (int g = 0; g < 3; g++) {
        bool bias_grp = (y == 10) && (g == 2);
#pragma unroll
        for (int tt = 0; tt < 4; tt++) {
            int t = g * 4 + tt;
            int nloc = t * 8 + nloc_base;
            float c[4] = {0.f, 0.f, 0.f, 0.f};
#pragma unroll
            for (int ch = 0; ch < 2; ch++) {
                int kb = ch * 16 + kc;
                uint32_t b0 = *reinterpret_cast<const uint32_t*>(sB + nloc * BSTR + kb);
                uint32_t b1 = *reinterpret_cast<const uint32_t*>(sB + nloc * BSTR + kb + 8);
                hmma16816(c, A0[ch], A1[ch], A2[ch], A3[ch], b0, b1);
            }
            if (bias_grp) {
                int o = (t - 8) * 8 + kc;   // cols 1024..1055
                if (n_row0 < N_NODES)
                    *reinterpret_cast<float2*>(g_Yb + (size_t)n_row0 * 32 + o) =
                        make_float2(c[0], c[1]);
                if (n_row1 < N_NODES)
                    *reinterpret_cast<float2*>(g_Yb + (size_t)n_row1 * 32 + o) =
                        make_float2(c[2], c[3]);
            } else {
                __nv_bfloat162 p0 = __floats2bfloat162_rn(c[0], c[1]);
                __nv_bfloat162 p1 = __floats2bfloat162_rn(c[2], c[3]);
                wstage[row * SROW + tt * 4 + kci] = *reinterpret_cast<unsigned*>(&p0);
                wstage[(row + 8) * SROW + tt * 4 + kci] = *reinterpret_cast<unsigned*>(&p1);
            }
        }
        if (!bias_grp) {
            __syncwarp();
            int row16 = lane >> 1;       // 0..15
            int half = lane & 1;
            int n = m0 + wid * 16 + row16;
#pragma unroll
            for (int i = 0; i < 2; i++) {
                int q = half * 2 + i;    // t within group
                uint4 v = *reinterpret_cast<uint4*>(wstage + row16 * SROW + q * 4);
                if (n < N_NODES)
                    *reinterpret_cast<uint4*>(g_Yt + (size_t)n * 512 +
                                              y * 48 + g * 16 + q * 4) = v;
            }
            __syncwarp();
        }
    }
}

// ---------------- edge kernel: warp per edge (grid-stride x4) ---------------
__global__ __launch_bounds__(256) void edge_kernel(
    const float* __restrict__ ea, const float* __restrict__ w1,
    const float* __restrict__ b1, float* __restrict__ agg) {
    __shared__ float sw1[16 * 32];
    __shared__ float sb1[32];
    int tid = threadIdx.x, lane = tid & 31, wid = tid >> 5;
    for (int i = tid; i < 512; i += 256) sw1[i] = w1[i];
    if (tid < 32) sb1[tid] = b1[tid];
    __syncthreads();

    for (int e = blockIdx.x * 8 + wid; e < N_EDGES; e += EGB * 8) {
        int s = g_src[e];
        int d = g_dst[e];

        const float4* eap = reinterpret_cast<const float4*>(ea + (size_t)e * 16);
        float acc = sb1[lane];
#pragma unroll
        for (int j = 0; j < 4; j++) {
            float4 av = __ldg(eap + j);
            acc = fmaf(av.x, sw1[(4 * j + 0) * 32 + lane], acc);
            acc = fmaf(av.y, sw1[(4 * j + 1) * 32 + lane], acc);
            acc = fmaf(av.z, sw1[(4 * j + 2) * 32 + lane], acc);
            acc = fmaf(av.w, sw1[(4 * j + 3) * 32 + lane], acc);
        }
        float he = fmaxf(acc, 0.f);

        float m0 = __ldg(g_Yb + (size_t)s * 32 + lane);
        float m1 = 0.f;
        const uint4* yp =
            reinterpret_cast<const uint4*>(g_Yt) + (size_t)s * 128 + lane * 4;
#pragma unroll
        for (int i = 0; i < 4; i++) {
            uint4 q = __ldg(yp + i);
            unsigned uu[4] = {q.x, q.y, q.z, q.w};
#pragma unroll
            for (int c = 0; c < 4; c++) {
                int k = i * 8 + c * 2;
                float lo = __int_as_float(uu[c] << 16);
                float hi = __int_as_float(uu[c] & 0xffff0000u);
                m0 = fmaf(__shfl_sync(0xffffffffu, he, k), lo, m0);
                m1 = fmaf(__shfl_sync(0xffffffffu, he, k + 1), hi, m1);
            }
        }
        atomicAdd(&agg[(size_t)d * 32 + lane], m0 + m1);
    }
}

// ---------------- node update (+ agg reset; + fused decoder on last) --------
__global__ __launch_bounds__(256) void node_update_kernel(
    const float* __restrict__ hin, float* __restrict__ agg,
    const float* __restrict__ cnt, const float* __restrict__ rW,
    const float* __restrict__ rb, float* __restrict__ hout, int last,
    const float* __restrict__ Wo, const float* __restrict__ bo,
    const float* __restrict__ W1, const float* __restrict__ b1d,
    const float* __restrict__ W2, const float* __restrict__ b2d,
    float* __restrict__ out) {
    __shared__ float sW[32 * 32];
    __shared__ float sb[32];
    __shared__ float sWo[32 * 16], sW1[16 * 32], sW2[32 * 64];
    __shared__ float sbo[16], sb1[32], sb2[64];
    int tid = threadIdx.x;
    for (int i = tid; i < 1024; i += 256) sW[i] = rW[i];
    if (tid < 32) sb[tid] = rb[tid];
    if (last) {
        for (int i = tid; i < 512; i += 256) { sWo[i] = Wo[i]; sW1[i] = W1[i]; }
        for (int i = tid; i < 2048; i += 256) sW2[i] = W2[i];
        if (tid < 16) sbo[tid] = bo[tid];
        if (tid < 32) sb1[tid] = b1d[tid];
        if (tid < 64) sb2[tid] = b2d[tid];
    }
    __syncthreads();
    int lane = tid & 31, wid = tid >> 5;
    int n = blockIdx.x * 8 + wid;
    if (n >= N_NODES) return;

    float a = agg[n * 32 + lane] / fmaxf(cnt[n], 1.f);
    float hv = hin[n * 32 + lane];
    float r = sb[lane] + a;
#pragma unroll
    for (int k = 0; k < 32; k++)
        r = fmaf(__shfl_sync(0xffffffffu, hv, k), sW[k * 32 + lane], r);
    float hnew = fmaxf(r, 0.f);

    if (!last) {
        agg[n * 32 + lane] = 0.f;   // reset for next layer's atomics
        hout[n * 32 + lane] = hnew;
        return;
    }

    // fused decoder: z = h'@Wo+bo; d1 = relu(z@W1+b1); out = d1@W2+b2
    int l16 = lane & 15;
    float z = sbo[l16];
#pragma unroll
    for (int k = 0; k < 32; k++)
        z = fmaf(__shfl_sync(0xffffffffu, hnew, k), sWo[k * 16 + l16], z);
    float d1 = sb1[lane];
#pragma unroll
    for (int j = 0; j < 16; j++)
        d1 = fmaf(__shfl_sync(0xffffffffu, z, j), sW1[j * 32 + lane], d1);
    d1 = fmaxf(d1, 0.f);
    float o0 = sb2[lane], o1 = sb2[32 + lane];
#pragma unroll
    for (int j = 0; j < 32; j++) {
        float dj = __shfl_sync(0xffffffffu, d1, j);
        o0 = fmaf(dj, sW2[j * 64 + lane], o0);
        o1 = fmaf(dj, sW2[j * 64 + 32 + lane], o1);
    }
    out[n * 64 + lane] = o0;
    out[n * 64 + 32 + lane] = o1;
}

// ---------------- launch ----------------
extern "C" void kernel_launch(void* const* d_in, const int* in_sizes, int n_in,
                              void* d_out, int out_size) {
    const float* x        = (const float*)d_in[0];
    const void*  ei       = d_in[1];
    const float* ea       = (const float*)d_in[2];
    const float* lin_in_w = (const float*)d_in[3];
    const float* lin_in_b = (const float*)d_in[4];
    const float* edge_w1  = (const float*)d_in[5];
    const float* edge_b1  = (const float*)d_in[6];
    const float* edge_w2  = (const float*)d_in[7];
    const float* edge_b2  = (const float*)d_in[8];
    const float* root_w   = (const float*)d_in[9];
    const float* root_b   = (const float*)d_in[10];
    const float* lout_w   = (const float*)d_in[11];
    const float* lout_b   = (const float*)d_in[12];
    const float* dec_w1   = (const float*)d_in[13];
    const float* dec_b1   = (const float*)d_in[14];
    const float* dec_w2   = (const float*)d_in[15];
    const float* dec_b2   = (const float*)d_in[16];
    float* out = (float*)d_out;

    void *p_agg, *p_cnt, *p_hA, *p_hB, *p_w2tb;
    cudaGetSymbolAddress(&p_agg, g_agg);
    cudaGetSymbolAddress(&p_cnt, g_cnt);
    cudaGetSymbolAddress(&p_hA, g_hA);
    cudaGetSymbolAddress(&p_hB, g_hB);
    cudaGetSymbolAddress(&p_w2tb, g_w2tb);
    float* hbuf[4] = {(float*)p_hA, (float*)p_hB, (float*)p_hA, (float*)p_hB};

    cudaMemsetAsync(p_cnt, 0, (size_t)N_NODES * sizeof(float), 0);
    cudaMemsetAsync(p_agg, 0, (size_t)N_NODES * HID * sizeof(float), 0);

    const int EB = (N_EDGES + 255) / 256;
    pre_kernel<<<EB, 256>>>(ei, (float*)p_cnt);
    w2tb_all_kernel<<<(3 * 33792 + 255) / 256, 256>>>(edge_w2, edge_b2);

    const int NB = (N_NODES + 7) / 8;
    inproj_kernel<<<NB, 256>>>(x, lin_in_w, lin_in_b, (float*)p_hA);

    dim3 ygrid(M_TILES, 11);
    for (int L = 0; L < 3; L++) {
        const float* w1 = edge_w1 + L * 16 * 32;
        const float* b1 = edge_b1 + L * 32;
        const float* rw = root_w + L * 32 * 32;
        const float* rb = root_b + L * 32;
        const float* hin = hbuf[L];
        float* hout = hbuf[L + 1];
        const unsigned short* w2tbL =
            (const unsigned short*)p_w2tb + (size_t)L * 33792;

        y_hmma_kernel<<<ygrid, 256>>>(hin, w2tbL);
        edge_kernel<<<EGB, 256>>>(ea, w1, b1, (float*)p_agg);
        node_update_kernel<<<NB, 256>>>(hin, (float*)p_agg, (const float*)p_cnt,
                                        rw, rb, hout, (L == 2) ? 1 : 0,
                                        lout_w, lout_b, dec_w1, dec_b1,
                                        dec_w2, dec_b2, out);
    }
}

// round 14
// speedup vs baseline: 1.0569x; 1.0569x over previous
#include <cuda_runtime.h>
#include <cuda_bf16.h>
#include <stdint.h>

#define N_NODES 50000
#define N_EDGES 200000
#define HID 32
#define M_TILES 391          // ceil(50000/128)
#define EGB 6250             // edge kernel blocks (4 edges/warp)

// ---------------- device scratch (static allocation only) ----------------
__device__ int            g_src[N_EDGES], g_dst[N_EDGES];
__device__ float          g_hA[N_NODES * HID];
__device__ float          g_hB[N_NODES * HID];
__device__ unsigned short g_w2tb[3 * 1056 * 32];       // bf16 [L][col][h]
__device__ unsigned       g_Yt[(size_t)N_NODES * 512]; // bf16x2 packed [n][o][k/2]
__device__ float          g_Yb[N_NODES * HID];         // bias image row (fp32)
__device__ float          g_agg[N_NODES * HID];
__device__ float          g_cnt[N_NODES];

// ---------------- fused pre: detect dtype + normalize + dst counts ----------
__global__ __launch_bounds__(256) void pre_kernel(const void* ei,
                                                  float* __restrict__ cnt) {
    __shared__ int any;
    if (threadIdx.x == 0) any = 0;
    __syncthreads();
    const unsigned* u = (const unsigned*)ei;
    int local = 0;
    for (int i = threadIdx.x; i < 2048; i += 256)
        if (u[2 * i + 1] != 0u) local = 1;
    if (local) atomicOr(&any, 1);
    __syncthreads();
    int is64 = (any == 0);

    int e = blockIdx.x * 256 + threadIdx.x;
    if (e >= N_EDGES) return;
    int s, d;
    if (is64) {
        const long long* p = (const long long*)ei;
        s = (int)p[e];
        d = (int)p[N_EDGES + e];
    } else {
        const int* p = (const int*)ei;
        s = p[e];
        d = p[N_EDGES + e];
    }
    s = min(max(s, 0), N_NODES - 1);
    d = min(max(d, 0), N_NODES - 1);
    g_src[e] = s;
    g_dst[e] = d;
    atomicAdd(&cnt[d], 1.f);
}

// ---------------- h0 = relu(x @ Win + b) ------------------------------------
__global__ __launch_bounds__(256) void inproj_kernel(
    const float* __restrict__ x, const float* __restrict__ W,
    const float* __restrict__ b, float* __restrict__ hout) {
    __shared__ float sW[64 * 32];
    __shared__ float sb[32];
    int tid = threadIdx.x;
    for (int i = tid; i < 64 * 32; i += 256) sW[i] = W[i];
    if (tid < 32) sb[tid] = b[tid];
    __syncthreads();
    int lane = tid & 31, wid = tid >> 5;
    int n = blockIdx.x * 8 + wid;
    if (n >= N_NODES) return;
    float xa = x[n * 64 + lane];
    float xb = x[n * 64 + 32 + lane];
    float r = sb[lane];
#pragma unroll
    for (int k = 0; k < 32; k++)
        r = fmaf(__shfl_sync(0xffffffffu, xa, k), sW[k * 32 + lane], r);
#pragma unroll
    for (int k = 0; k < 32; k++)
        r = fmaf(__shfl_sync(0xffffffffu, xb, k), sW[(k + 32) * 32 + lane], r);
    hout[n * 32 + lane] = fmaxf(r, 0.f);
}

// ---------------- w2 repack (all 3 layers, one launch) ----------------------
__global__ __launch_bounds__(256) void w2tb_all_kernel(
    const float* __restrict__ edge_w2, const float* __restrict__ edge_b2) {
    int idx = blockIdx.x * 256 + threadIdx.x;
    if (idx >= 3 * 33792) return;
    int L = idx / 33792;
    int rem = idx - L * 33792;
    int col = rem >> 5, hh = rem & 31;
    const float* w2 = edge_w2 + L * 32768;
    const float* b2 = edge_b2 + L * 1024;
    float v;
    if (col < 1024) {
        int o = col >> 5, k = col & 31;
        v = w2[k * 1024 + hh * 32 + o];
    } else {
        v = b2[hh * 32 + (col - 1024)];
    }
    __nv_bfloat16 bv = __float2bfloat16(v);
    g_w2tb[idx] = *reinterpret_cast<unsigned short*>(&bv);
}

// ---------------- Y via mma.sync bf16 HMMA ----------------------------------
__device__ __forceinline__ void hmma16816(float* c, uint32_t a0, uint32_t a1,
                                          uint32_t a2, uint32_t a3,
                                          uint32_t b0, uint32_t b1) {
    asm volatile(
        "mma.sync.aligned.m16n8k16.row.col.f32.bf16.bf16.f32 "
        "{%0,%1,%2,%3}, {%4,%5,%6,%7}, {%8,%9}, {%0,%1,%2,%3};"
        : "+f"(c[0]), "+f"(c[1]), "+f"(c[2]), "+f"(c[3])
        : "r"(a0), "r"(a1), "r"(a2), "r"(a3), "r"(b0), "r"(b1));
}

#define ASTR 36
#define BSTR 36

__global__ __launch_bounds__(256) void y_hmma_kernel(
    const float* __restrict__ h, const unsigned short* __restrict__ w2tb) {
    __shared__ __nv_bfloat16 sA[128 * ASTR];
    __shared__ __nv_bfloat16 sB[264 * BSTR];
    int tid = threadIdx.x, lane = tid & 31, wid = tid >> 5;
    int m0 = blockIdx.x * 128;
    int nb0 = blockIdx.y * 264;

    // vectorized A staging: each thread loads one float4 x4 rows -> bf16x2 STS
    {
        int r = tid >> 1;            // 0..127
        int q = tid & 1;             // half-row (16 floats)
        int n = m0 + r;
        const float4* hp = reinterpret_cast<const float4*>(h + (size_t)n * 32) + q * 4;
        unsigned* dst = reinterpret_cast<unsigned*>(sA + r * ASTR + q * 16);
#pragma unroll
        for (int i = 0; i < 4; i++) {
            float4 v = (n < N_NODES) ? __ldg(hp + i)
                                     : make_float4(0.f, 0.f, 0.f, 0.f);
            __nv_bfloat162 p0 = __floats2bfloat162_rn(v.x, v.y);
            __nv_bfloat162 p1 = __floats2bfloat162_rn(v.z, v.w);
            dst[i * 2 + 0] = *reinterpret_cast<unsigned*>(&p0);
            dst[i * 2 + 1] = *reinterpret_cast<unsigned*>(&p1);
        }
    }
    for (int idx = tid; idx < 264 * 32; idx += 256) {
        int r = idx >> 5, k = idx & 31;
        unsigned short us = w2tb[(nb0 + r) * 32 + k];
        sB[r * BSTR + k] = *reinterpret_cast<__nv_bfloat16*>(&us);
    }
    __syncthreads();

    int r = wid * 16 + (lane >> 2);
    int kc = (lane & 3) * 2;
    uint32_t A0[2], A1[2], A2[2], A3[2];
#pragma unroll
    for (int ch = 0; ch < 2; ch++) {
        int kb = ch * 16 + kc;
        A0[ch] = *reinterpret_cast<const uint32_t*>(sA + r * ASTR + kb);
        A1[ch] = *reinterpret_cast<const uint32_t*>(sA + (r + 8) * ASTR + kb);
        A2[ch] = *reinterpret_cast<const uint32_t*>(sA + r * ASTR + kb + 8);
        A3[ch] = *reinterpret_cast<const uint32_t*>(sA + (r + 8) * ASTR + kb + 8);
    }

    int n_row0 = m0 + r;
    int n_row1 = n_row0 + 8;
    int nloc_base = lane >> 2;

    for (int t = 0; t < 33; t++) {
        int nloc = t * 8 + nloc_base;
        float c[4] = {0.f, 0.f, 0.f, 0.f};
#pragma unroll
        for (int ch = 0; ch < 2; ch++) {
            int kb = ch * 16 + kc;
            uint32_t b0 = *reinterpret_cast<const uint32_t*>(sB + nloc * BSTR + kb);
            uint32_t b1 = *reinterpret_cast<const uint32_t*>(sB + nloc * BSTR + kb + 8);
            hmma16816(c, A0[ch], A1[ch], A2[ch], A3[ch], b0, b1);
        }
        int col = nb0 + t * 8 + kc;
        if (col < 1024) {
            int o = col >> 5, kk = col & 31;
            __nv_bfloat162 p0 = __floats2bfloat162_rn(c[0], c[1]);
            __nv_bfloat162 p1 = __floats2bfloat162_rn(c[2], c[3]);
            if (n_row0 < N_NODES)
                g_Yt[(size_t)n_row0 * 512 + o * 16 + (kk >> 1)] =
                    *reinterpret_cast<unsigned*>(&p0);
            if (n_row1 < N_NODES)
                g_Yt[(size_t)n_row1 * 512 + o * 16 + (kk >> 1)] =
                    *reinterpret_cast<unsigned*>(&p1);
        } else {
            int o = col - 1024;
            if (n_row0 < N_NODES)
                *reinterpret_cast<float2*>(g_Yb + (size_t)n_row0 * 32 + o) =
                    make_float2(c[0], c[1]);
            if (n_row1 < N_NODES)
                *reinterpret_cast<float2*>(g_Yb + (size_t)n_row1 * 32 + o) =
                    make_float2(c[2], c[3]);
        }
    }
}

// ---------------- edge kernel: warp per edge, chains broken 4-wide ----------
__global__ __launch_bounds__(256) void edge_kernel(
    const float* __restrict__ ea, const float* __restrict__ w1,
    const float* __restrict__ b1, float* __restrict__ agg) {
    __shared__ float sw1[16 * 32];
    __shared__ float sb1[32];
    int tid = threadIdx.x, lane = tid & 31, wid = tid >> 5;
    for (int i = tid; i < 512; i += 256) sw1[i] = w1[i];
    if (tid < 32) sb1[tid] = b1[tid];
    __syncthreads();

#pragma unroll 2
    for (int e = blockIdx.x * 8 + wid; e < N_EDGES; e += EGB * 8) {
        int s = g_src[e];
        int d = g_dst[e];

        const float4* eap = reinterpret_cast<const float4*>(ea + (size_t)e * 16);
        float acA = sb1[lane], acB = 0.f;
#pragma unroll
        for (int j = 0; j < 2; j++) {
            float4 a0 = __ldg(eap + j);
            float4 a1 = __ldg(eap + j + 2);
            acA = fmaf(a0.x, sw1[(4 * j + 0) * 32 + lane], acA);
            acB = fmaf(a1.x, sw1[(4 * j + 8) * 32 + lane], acB);
            acA = fmaf(a0.y, sw1[(4 * j + 1) * 32 + lane], acA);
            acB = fmaf(a1.y, sw1[(4 * j + 9) * 32 + lane], acB);
            acA = fmaf(a0.z, sw1[(4 * j + 2) * 32 + lane], acA);
            acB = fmaf(a1.z, sw1[(4 * j + 10) * 32 + lane], acB);
            acA = fmaf(a0.w, sw1[(4 * j + 3) * 32 + lane], acA);
            acB = fmaf(a1.w, sw1[(4 * j + 11) * 32 + lane], acB);
        }
        float he = fmaxf(acA + acB, 0.f);

        float m0 = __ldg(g_Yb + (size_t)s * 32 + lane);
        float m1 = 0.f, m2 = 0.f, m3 = 0.f;
        const uint4* yp =
            reinterpret_cast<const uint4*>(g_Yt) + (size_t)s * 128 + lane * 4;
#pragma unroll
        for (int i = 0; i < 4; i++) {
            uint4 q = __ldg(yp + i);
            unsigned uu[4] = {q.x, q.y, q.z, q.w};
#pragma unroll
            for (int c = 0; c < 4; c += 2) {
                int k = i * 8 + c * 2;
                float lo0 = __int_as_float(uu[c] << 16);
                float hi0 = __int_as_float(uu[c] & 0xffff0000u);
                float lo1 = __int_as_float(uu[c + 1] << 16);
                float hi1 = __int_as_float(uu[c + 1] & 0xffff0000u);
                m0 = fmaf(__shfl_sync(0xffffffffu, he, k), lo0, m0);
                m1 = fmaf(__shfl_sync(0xffffffffu, he, k + 1), hi0, m1);
                m2 = fmaf(__shfl_sync(0xffffffffu, he, k + 2), lo1, m2);
                m3 = fmaf(__shfl_sync(0xffffffffu, he, k + 3), hi1, m3);
            }
        }
        atomicAdd(&agg[(size_t)d * 32 + lane], (m0 + m1) + (m2 + m3));
    }
}

// ---------------- node update (+ agg reset; + fused decoder on last) --------
__global__ __launch_bounds__(256) void node_update_kernel(
    const float* __restrict__ hin, float* __restrict__ agg,
    const float* __restrict__ cnt, const float* __restrict__ rW,
    const float* __restrict__ rb, float* __restrict__ hout, int last,
    const float* __restrict__ Wo, const float* __restrict__ bo,
    const float* __restrict__ W1, const float* __restrict__ b1d,
    const float* __restrict__ W2, const float* __restrict__ b2d,
    float* __restrict__ out) {
    __shared__ float sW[32 * 32];
    __shared__ float sb[32];
    __shared__ float sWo[32 * 16], sW1[16 * 32], sW2[32 * 64];
    __shared__ float sbo[16], sb1[32], sb2[64];
    int tid = threadIdx.x;
    for (int i = tid; i < 1024; i += 256) sW[i] = rW[i];
    if (tid < 32) sb[tid] = rb[tid];
    if (last) {
        for (int i = tid; i < 512; i += 256) { sWo[i] = Wo[i]; sW1[i] = W1[i]; }
        for (int i = tid; i < 2048; i += 256) sW2[i] = W2[i];
        if (tid < 16) sbo[tid] = bo[tid];
        if (tid < 32) sb1[tid] = b1d[tid];
        if (tid < 64) sb2[tid] = b2d[tid];
    }
    __syncthreads();
    int lane = tid & 31, wid = tid >> 5;
    int n = blockIdx.x * 8 + wid;
    if (n >= N_NODES) return;

    float a = agg[n * 32 + lane] / fmaxf(cnt[n], 1.f);
    float hv = hin[n * 32 + lane];
    float r = sb[lane] + a;
#pragma unroll
    for (int k = 0; k < 32; k++)
        r = fmaf(__shfl_sync(0xffffffffu, hv, k), sW[k * 32 + lane], r);
    float hnew = fmaxf(r, 0.f);

    if (!last) {
        agg[n * 32 + lane] = 0.f;   // reset for next layer's atomics
        hout[n * 32 + lane] = hnew;
        return;
    }

    // fused decoder: z = h'@Wo+bo; d1 = relu(z@W1+b1); out = d1@W2+b2
    int l16 = lane & 15;
    float z = sbo[l16];
#pragma unroll
    for (int k = 0; k < 32; k++)
        z = fmaf(__shfl_sync(0xffffffffu, hnew, k), sWo[k * 16 + l16], z);
    float d1 = sb1[lane];
#pragma unroll
    for (int j = 0; j < 16; j++)
        d1 = fmaf(__shfl_sync(0xffffffffu, z, j), sW1[j * 32 + lane], d1);
    d1 = fmaxf(d1, 0.f);
    float o0 = sb2[lane], o1 = sb2[32 + lane];
#pragma unroll
    for (int j = 0; j < 32; j++) {
        float dj = __shfl_sync(0xffffffffu, d1, j);
        o0 = fmaf(dj, sW2[j * 64 + lane], o0);
        o1 = fmaf(dj, sW2[j * 64 + 32 + lane], o1);
    }
    out[n * 64 + lane] = o0;
    out[n * 64 + 32 + lane] = o1;
}

// ---------------- launch ----------------
extern "C" void kernel_launch(void* const* d_in, const int* in_sizes, int n_in,
                              void* d_out, int out_size) {
    const float* x        = (const float*)d_in[0];
    const void*  ei       = d_in[1];
    const float* ea       = (const float*)d_in[2];
    const float* lin_in_w = (const float*)d_in[3];
    const float* lin_in_b = (const float*)d_in[4];
    const float* edge_w1  = (const float*)d_in[5];
    const float* edge_b1  = (const float*)d_in[6];
    const float* edge_w2  = (const float*)d_in[7];
    const float* edge_b2  = (const float*)d_in[8];
    const float* root_w   = (const float*)d_in[9];
    const float* root_b   = (const float*)d_in[10];
    const float* lout_w   = (const float*)d_in[11];
    const float* lout_b   = (const float*)d_in[12];
    const float* dec_w1   = (const float*)d_in[13];
    const float* dec_b1   = (const float*)d_in[14];
    const float* dec_w2   = (const float*)d_in[15];
    const float* dec_b2   = (const float*)d_in[16];
    float* out = (float*)d_out;

    void *p_agg, *p_cnt, *p_hA, *p_hB, *p_w2tb;
    cudaGetSymbolAddress(&p_agg, g_agg);
    cudaGetSymbolAddress(&p_cnt, g_cnt);
    cudaGetSymbolAddress(&p_hA, g_hA);
    cudaGetSymbolAddress(&p_hB, g_hB);
    cudaGetSymbolAddress(&p_w2tb, g_w2tb);
    float* hbuf[4] = {(float*)p_hA, (float*)p_hB, (float*)p_hA, (float*)p_hB};

    cudaMemsetAsync(p_cnt, 0, (size_t)N_NODES * sizeof(float), 0);
    cudaMemsetAsync(p_agg, 0, (size_t)N_NODES * HID * sizeof(float), 0);

    const int EB = (N_EDGES + 255) / 256;
    pre_kernel<<<EB, 256>>>(ei, (float*)p_cnt);
    w2tb_all_kernel<<<(3 * 33792 + 255) / 256, 256>>>(edge_w2, edge_b2);

    const int NB = (N_NODES + 7) / 8;
    inproj_kernel<<<NB, 256>>>(x, lin_in_w, lin_in_b, (float*)p_hA);

    dim3 ygrid(M_TILES, 4);
    for (int L = 0; L < 3; L++) {
        const float* w1 = edge_w1 + L * 16 * 32;
        const float* b1 = edge_b1 + L * 32;
        const float* rw = root_w + L * 32 * 32;
        const float* rb = root_b + L * 32;
        const float* hin = hbuf[L];
        float* hout = hbuf[L + 1];
        const unsigned short* w2tbL =
            (const unsigned short*)p_w2tb + (size_t)L * 33792;

        y_hmma_kernel<<<ygrid, 256>>>(hin, w2tbL);
        edge_kernel<<<EGB, 256>>>(ea, w1, b1, (float*)p_agg);
        node_update_kernel<<<NB, 256>>>(hin, (float*)p_agg, (const float*)p_cnt,
                                        rw, rb, hout, (L == 2) ? 1 : 0,
                                        lout_w, lout_b, dec_w1, dec_b1,
                                        dec_w2, dec_b2, out);
    }
}

// round 15
// speedup vs baseline: 1.3607x; 1.2874x over previous
#include <cuda_runtime.h>
#include <cuda_bf16.h>
#include <stdint.h>

#define N_NODES 50000
#define N_EDGES 200000
#define HID 32
#define SB_NODES 16
#define NBKT 3125            // 50000 / 16 exactly
#define BCAP 512

// ---------------- device scratch (static allocation only) ----------------
__device__ int            g_src[N_EDGES], g_dst[N_EDGES];
__device__ float          g_hA[N_NODES * HID];
__device__ float          g_hB[N_NODES * HID];
__device__ unsigned short g_w2tb[3 * 1056 * 32];   // bf16 [L][col][h]; col=o*32+k, 1024+o=bias
__device__ float          g_agg[N_NODES * HID];
__device__ float          g_cnt[N_NODES];
__device__ int            g_bkt[NBKT * BCAP];
__device__ int            g_bcnt[NBKT];

// ---------------- fused pre: detect + normalize + dst counts + buckets ------
__global__ __launch_bounds__(256) void pre_kernel(const void* ei,
                                                  float* __restrict__ cnt) {
    __shared__ int any;
    if (threadIdx.x == 0) any = 0;
    __syncthreads();
    const unsigned* u = (const unsigned*)ei;
    int local = 0;
    for (int i = threadIdx.x; i < 2048; i += 256)
        if (u[2 * i + 1] != 0u) local = 1;
    if (local) atomicOr(&any, 1);
    __syncthreads();
    int is64 = (any == 0);

    int e = blockIdx.x * 256 + threadIdx.x;
    if (e >= N_EDGES) return;
    int s, d;
    if (is64) {
        const long long* p = (const long long*)ei;
        s = (int)p[e];
        d = (int)p[N_EDGES + e];
    } else {
        const int* p = (const int*)ei;
        s = p[e];
        d = p[N_EDGES + e];
    }
    s = min(max(s, 0), N_NODES - 1);
    d = min(max(d, 0), N_NODES - 1);
    g_src[e] = s;
    g_dst[e] = d;
    atomicAdd(&cnt[d], 1.f);
    int b = s >> 4;
    int p = atomicAdd(&g_bcnt[b], 1);
    if (p < BCAP) g_bkt[b * BCAP + p] = e;
}

// ---------------- h0 = relu(x @ Win + b) ------------------------------------
__global__ __launch_bounds__(256) void inproj_kernel(
    const float* __restrict__ x, const float* __restrict__ W,
    const float* __restrict__ b, float* __restrict__ hout) {
    __shared__ float sW[64 * 32];
    __shared__ float sb[32];
    int tid = threadIdx.x;
    for (int i = tid; i < 64 * 32; i += 256) sW[i] = W[i];
    if (tid < 32) sb[tid] = b[tid];
    __syncthreads();
    int lane = tid & 31, wid = tid >> 5;
    int n = blockIdx.x * 8 + wid;
    if (n >= N_NODES) return;
    float xa = x[n * 64 + lane];
    float xb = x[n * 64 + 32 + lane];
    float r = sb[lane];
#pragma unroll
    for (int k = 0; k < 32; k++)
        r = fmaf(__shfl_sync(0xffffffffu, xa, k), sW[k * 32 + lane], r);
#pragma unroll
    for (int k = 0; k < 32; k++)
        r = fmaf(__shfl_sync(0xffffffffu, xb, k), sW[(k + 32) * 32 + lane], r);
    hout[n * 32 + lane] = fmaxf(r, 0.f);
}

// ---------------- w2 repack (all 3 layers, one launch) ----------------------
__global__ __launch_bounds__(256) void w2tb_all_kernel(
    const float* __restrict__ edge_w2, const float* __restrict__ edge_b2) {
    int idx = blockIdx.x * 256 + threadIdx.x;
    if (idx >= 3 * 33792) return;
    int L = idx / 33792;
    int rem = idx - L * 33792;
    int col = rem >> 5, hh = rem & 31;
    const float* w2 = edge_w2 + L * 32768;
    const float* b2 = edge_b2 + L * 1024;
    float v;
    if (col < 1024) {
        int o = col >> 5, k = col & 31;
        v = w2[k * 1024 + hh * 32 + o];
    } else {
        v = b2[hh * 32 + (col - 1024)];
    }
    __nv_bfloat16 bv = __float2bfloat16(v);
    g_w2tb[idx] = *reinterpret_cast<unsigned short*>(&bv);
}

// ---------------- HMMA helper -----------------------------------------------
__device__ __forceinline__ void hmma16816(float* c, uint32_t a0, uint32_t a1,
                                          uint32_t a2, uint32_t a3,
                                          uint32_t b0, uint32_t b1) {
    asm volatile(
        "mma.sync.aligned.m16n8k16.row.col.f32.bf16.bf16.f32 "
        "{%0,%1,%2,%3}, {%4,%5,%6,%7}, {%8,%9}, {%0,%1,%2,%3};"
        : "+f"(c[0]), "+f"(c[1]), "+f"(c[2]), "+f"(c[3])
        : "r"(a0), "r"(a1), "r"(a2), "r"(a3), "r"(b0), "r"(b1));
}

// ---------------- fused layer: Y in smem + edge apply -----------------------
// Block = 16 source nodes. Phase 1: HMMA [16x32]@[32x1056] -> smem Y (packed
// bf16x2, s-stride 561 u32, o-stride 17) + fp32 bias tile. Phase 2: this
// block's src-bucketed edges read Y from smem, atomically scatter to agg.
#define Y_OSTR 17
#define Y_SSTR 561   // 33*17: STS <=2-way conflict, edge LDS conflict-free

__global__ __launch_bounds__(256) void fused_layer_kernel(
    const float* __restrict__ h, const unsigned short* __restrict__ w2tb,
    const float* __restrict__ ea, const float* __restrict__ w1,
    const float* __restrict__ b1, float* __restrict__ agg) {
    __shared__ unsigned sY[SB_NODES * Y_SSTR];   // 35.9 KB
    __shared__ float sBias[SB_NODES * 32];
    __shared__ __nv_bfloat16 sA[SB_NODES * 36];
    __shared__ float sw1[16 * 32];
    __shared__ float sb1[32];

    int tid = threadIdx.x, lane = tid & 31, wid = tid >> 5;
    int s0 = blockIdx.x * SB_NODES;

    for (int i = tid; i < 512; i += 256) {
        sw1[i] = w1[i];
        int r = i >> 5, k = i & 31;
        sA[r * 36 + k] = __float2bfloat16(__ldg(h + (size_t)(s0 + r) * 32 + k));
    }
    if (tid < 32) sb1[tid] = b1[tid];
    __syncthreads();

    // ---- Phase 1: MMA. All warps share the single m16 A-fragment.
    int r = lane >> 2;            // 0..7
    int kc = (lane & 3) * 2;
    uint32_t A0[2], A1[2], A2[2], A3[2];
#pragma unroll
    for (int ch = 0; ch < 2; ch++) {
        int kb = ch * 16 + kc;
        A0[ch] = *reinterpret_cast<const uint32_t*>(sA + r * 36 + kb);
        A1[ch] = *reinterpret_cast<const uint32_t*>(sA + (r + 8) * 36 + kb);
        A2[ch] = *reinterpret_cast<const uint32_t*>(sA + r * 36 + kb + 8);
        A3[ch] = *reinterpret_cast<const uint32_t*>(sA + (r + 8) * 36 + kb + 8);
    }

    for (int t = wid; t < 132; t += 8) {
        int nloc = t * 8 + (lane >> 2);
        float c[4] = {0.f, 0.f, 0.f, 0.f};
#pragma unroll
        for (int ch = 0; ch < 2; ch++) {
            int kb = ch * 16 + kc;
            uint32_t b0 = *reinterpret_cast<const uint32_t*>(w2tb + nloc * 32 + kb);
            uint32_t b1v = *reinterpret_cast<const uint32_t*>(w2tb + nloc * 32 + kb + 8);
            hmma16816(c, A0[ch], A1[ch], A2[ch], A3[ch], b0, b1v);
        }
        int col = t * 8 + kc;
        if (col < 1024) {
            int o = col >> 5, pr = (col & 31) >> 1;
            __nv_bfloat162 p0 = __floats2bfloat162_rn(c[0], c[1]);
            __nv_bfloat162 p1 = __floats2bfloat162_rn(c[2], c[3]);
            sY[r * Y_SSTR + o * Y_OSTR + pr] = *reinterpret_cast<unsigned*>(&p0);
            sY[(r + 8) * Y_SSTR + o * Y_OSTR + pr] = *reinterpret_cast<unsigned*>(&p1);
        } else {
            int o = col - 1024;
            *reinterpret_cast<float2*>(sBias + r * 32 + o) = make_float2(c[0], c[1]);
            *reinterpret_cast<float2*>(sBias + (r + 8) * 32 + o) = make_float2(c[2], c[3]);
        }
    }
    __syncthreads();

    // ---- Phase 2: this bucket's edges. lane = output o.
    int cnt = min(g_bcnt[blockIdx.x], BCAP);
    const int* list = g_bkt + blockIdx.x * BCAP;
    for (int idx = wid; idx < cnt; idx += 8) {
        int e = list[idx];
        int s = g_src[e] - s0;
        int d = g_dst[e];

        const float4* eap = reinterpret_cast<const float4*>(ea + (size_t)e * 16);
        float acA = sb1[lane], acB = 0.f;
#pragma unroll
        for (int j = 0; j < 2; j++) {
            float4 a0 = __ldg(eap + j);
            float4 a1 = __ldg(eap + j + 2);
            acA = fmaf(a0.x, sw1[(4 * j + 0) * 32 + lane], acA);
            acB = fmaf(a1.x, sw1[(4 * j + 8) * 32 + lane], acB);
            acA = fmaf(a0.y, sw1[(4 * j + 1) * 32 + lane], acA);
            acB = fmaf(a1.y, sw1[(4 * j + 9) * 32 + lane], acB);
            acA = fmaf(a0.z, sw1[(4 * j + 2) * 32 + lane], acA);
            acB = fmaf(a1.z, sw1[(4 * j + 10) * 32 + lane], acB);
            acA = fmaf(a0.w, sw1[(4 * j + 3) * 32 + lane], acA);
            acB = fmaf(a1.w, sw1[(4 * j + 11) * 32 + lane], acB);
        }
        float he = fmaxf(acA + acB, 0.f);

        const unsigned* yb = sY + s * Y_SSTR + lane * Y_OSTR;
        float m0 = sBias[s * 32 + lane], m1 = 0.f, m2 = 0.f, m3 = 0.f;
#pragma unroll
        for (int p = 0; p < 16; p += 4) {
            unsigned u0 = yb[p], u1 = yb[p + 1], u2 = yb[p + 2], u3 = yb[p + 3];
            m0 = fmaf(__shfl_sync(0xffffffffu, he, 2 * p + 0), __int_as_float(u0 << 16), m0);
            m1 = fmaf(__shfl_sync(0xffffffffu, he, 2 * p + 1), __int_as_float(u0 & 0xffff0000u), m1);
            m2 = fmaf(__shfl_sync(0xffffffffu, he, 2 * p + 2), __int_as_float(u1 << 16), m2);
            m3 = fmaf(__shfl_sync(0xffffffffu, he, 2 * p + 3), __int_as_float(u1 & 0xffff0000u), m3);
            m0 = fmaf(__shfl_sync(0xffffffffu, he, 2 * p + 4), __int_as_float(u2 << 16), m0);
            m1 = fmaf(__shfl_sync(0xffffffffu, he, 2 * p + 5), __int_as_float(u2 & 0xffff0000u), m1);
            m2 = fmaf(__shfl_sync(0xffffffffu, he, 2 * p + 6), __int_as_float(u3 << 16), m2);
            m3 = fmaf(__shfl_sync(0xffffffffu, he, 2 * p + 7), __int_as_float(u3 & 0xffff0000u), m3);
        }
        atomicAdd(&agg[(size_t)d * 32 + lane], (m0 + m1) + (m2 + m3));
    }
}

// ---------------- node update (+ agg reset; + fused decoder on last) --------
__global__ __launch_bounds__(256) void node_update_kernel(
    const float* __restrict__ hin, float* __restrict__ agg,
    const float* __restrict__ cnt, const float* __restrict__ rW,
    const float* __restrict__ rb, float* __restrict__ hout, int last,
    const float* __restrict__ Wo, const float* __restrict__ bo,
    const float* __restrict__ W1, const float* __restrict__ b1d,
    const float* __restrict__ W2, const float* __restrict__ b2d,
    float* __restrict__ out) {
    __shared__ float sW[32 * 32];
    __shared__ float sb[32];
    __shared__ float sWo[32 * 16], sW1[16 * 32], sW2[32 * 64];
    __shared__ float sbo[16], sb1[32], sb2[64];
    int tid = threadIdx.x;
    for (int i = tid; i < 1024; i += 256) sW[i] = rW[i];
    if (tid < 32) sb[tid] = rb[tid];
    if (last) {
        for (int i = tid; i < 512; i += 256) { sWo[i] = Wo[i]; sW1[i] = W1[i]; }
        for (int i = tid; i < 2048; i += 256) sW2[i] = W2[i];
        if (tid < 16) sbo[tid] = bo[tid];
        if (tid < 32) sb1[tid] = b1d[tid];
        if (tid < 64) sb2[tid] = b2d[tid];
    }
    __syncthreads();
    int lane = tid & 31, wid = tid >> 5;
    int n = blockIdx.x * 8 + wid;
    if (n >= N_NODES) return;

    float a = agg[n * 32 + lane] / fmaxf(cnt[n], 1.f);
    float hv = hin[n * 32 + lane];
    float r = sb[lane] + a;
#pragma unroll
    for (int k = 0; k < 32; k++)
        r = fmaf(__shfl_sync(0xffffffffu, hv, k), sW[k * 32 + lane], r);
    float hnew = fmaxf(r, 0.f);

    if (!last) {
        agg[n * 32 + lane] = 0.f;   // reset for next layer's atomics
        hout[n * 32 + lane] = hnew;
        return;
    }

    int l16 = lane & 15;
    float z = sbo[l16];
#pragma unroll
    for (int k = 0; k < 32; k++)
        z = fmaf(__shfl_sync(0xffffffffu, hnew, k), sWo[k * 16 + l16], z);
    float d1 = sb1[lane];
#pragma unroll
    for (int j = 0; j < 16; j++)
        d1 = fmaf(__shfl_sync(0xffffffffu, z, j), sW1[j * 32 + lane], d1);
    d1 = fmaxf(d1, 0.f);
    float o0 = sb2[lane], o1 = sb2[32 + lane];
#pragma unroll
    for (int j = 0; j < 32; j++) {
        float dj = __shfl_sync(0xffffffffu, d1, j);
        o0 = fmaf(dj, sW2[j * 64 + lane], o0);
        o1 = fmaf(dj, sW2[j * 64 + 32 + lane], o1);
    }
    out[n * 64 + lane] = o0;
    out[n * 64 + 32 + lane] = o1;
}

// ---------------- launch ----------------
extern "C" void kernel_launch(void* const* d_in, const int* in_sizes, int n_in,
                              void* d_out, int out_size) {
    const float* x        = (const float*)d_in[0];
    const void*  ei       = d_in[1];
    const float* ea       = (const float*)d_in[2];
    const float* lin_in_w = (const float*)d_in[3];
    const float* lin_in_b = (const float*)d_in[4];
    const float* edge_w1  = (const float*)d_in[5];
    const float* edge_b1  = (const float*)d_in[6];
    const float* edge_w2  = (const float*)d_in[7];
    const float* edge_b2  = (const float*)d_in[8];
    const float* root_w   = (const float*)d_in[9];
    const float* root_b   = (const float*)d_in[10];
    const float* lout_w   = (const float*)d_in[11];
    const float* lout_b   = (const float*)d_in[12];
    const float* dec_w1   = (const float*)d_in[13];
    const float* dec_b1   = (const float*)d_in[14];
    const float* dec_w2   = (const float*)d_in[15];
    const float* dec_b2   = (const float*)d_in[16];
    float* out = (float*)d_out;

    void *p_agg, *p_cnt, *p_hA, *p_hB, *p_w2tb, *p_bcnt;
    cudaGetSymbolAddress(&p_agg, g_agg);
    cudaGetSymbolAddress(&p_cnt, g_cnt);
    cudaGetSymbolAddress(&p_hA, g_hA);
    cudaGetSymbolAddress(&p_hB, g_hB);
    cudaGetSymbolAddress(&p_w2tb, g_w2tb);
    cudaGetSymbolAddress(&p_bcnt, g_bcnt);
    float* hbuf[4] = {(float*)p_hA, (float*)p_hB, (float*)p_hA, (float*)p_hB};

    cudaMemsetAsync(p_cnt, 0, (size_t)N_NODES * sizeof(float), 0);
    cudaMemsetAsync(p_agg, 0, (size_t)N_NODES * HID * sizeof(float), 0);
    cudaMemsetAsync(p_bcnt, 0, (size_t)NBKT * sizeof(int), 0);

    const int EB = (N_EDGES + 255) / 256;
    pre_kernel<<<EB, 256>>>(ei, (float*)p_cnt);
    w2tb_all_kernel<<<(3 * 33792 + 255) / 256, 256>>>(edge_w2, edge_b2);

    const int NB = (N_NODES + 7) / 8;
    inproj_kernel<<<NB, 256>>>(x, lin_in_w, lin_in_b, (float*)p_hA);

    for (int L = 0; L < 3; L++) {
        const float* w1 = edge_w1 + L * 16 * 32;
        const float* b1 = edge_b1 + L * 32;
        const float* rw = root_w + L * 32 * 32;
        const float* rb = root_b + L * 32;
        const float* hin = hbuf[L];
        float* hout = hbuf[L + 1];
        const unsigned short* w2tbL =
            (const unsigned short*)p_w2tb + (size_t)L * 33792;

        fused_layer_kernel<<<NBKT, 256>>>(hin, w2tbL, ea, w1, b1, (float*)p_agg);
        node_update_kernel<<<NB, 256>>>(hin, (float*)p_agg, (const float*)p_cnt,
                                        rw, rb, hout, (L == 2) ? 1 : 0,
                                        lout_w, lout_b, dec_w1, dec_b1,
                                        dec_w2, dec_b2, out);
    }
}

// round 16
// speedup vs baseline: 1.7189x; 1.2633x over previous
#include <cuda_runtime.h>
#include <cuda_bf16.h>
#include <stdint.h>

#define N_NODES 50000
#define N_EDGES 200000
#define HID 32
#define SB_NODES 16
#define NBKT 3125            // 50000 / 16 exactly
#define BCAP 512
#define Y_OSTR 260           // [o][s][pair] layout: o-stride in u32 (16*16 + 4 pad)

// ---------------- device scratch (static allocation only) ----------------
__device__ int   g_src[N_EDGES], g_dst[N_EDGES];
__device__ float g_hA[N_NODES * HID];
__device__ float g_hB[N_NODES * HID];
__device__ uint2 g_w2f[3 * 132 * 2 * 32];   // B fragments: [L][tile][chunk][lane]
__device__ float g_agg[N_NODES * HID];
__device__ float g_cnt[N_NODES];
__device__ int   g_bkt[NBKT * BCAP];
__device__ int   g_bcnt[NBKT];

// ---------------- fused pre: detect + normalize + dst counts + buckets ------
__global__ __launch_bounds__(256) void pre_kernel(const void* ei,
                                                  float* __restrict__ cnt) {
    __shared__ int any;
    if (threadIdx.x == 0) any = 0;
    __syncthreads();
    const unsigned* u = (const unsigned*)ei;
    int local = 0;
    for (int i = threadIdx.x; i < 2048; i += 256)
        if (u[2 * i + 1] != 0u) local = 1;
    if (local) atomicOr(&any, 1);
    __syncthreads();
    int is64 = (any == 0);

    int e = blockIdx.x * 256 + threadIdx.x;
    if (e >= N_EDGES) return;
    int s, d;
    if (is64) {
        const long long* p = (const long long*)ei;
        s = (int)p[e];
        d = (int)p[N_EDGES + e];
    } else {
        const int* p = (const int*)ei;
        s = p[e];
        d = p[N_EDGES + e];
    }
    s = min(max(s, 0), N_NODES - 1);
    d = min(max(d, 0), N_NODES - 1);
    g_src[e] = s;
    g_dst[e] = d;
    atomicAdd(&cnt[d], 1.f);
    int b = s >> 4;
    int p = atomicAdd(&g_bcnt[b], 1);
    if (p < BCAP) g_bkt[b * BCAP + p] = e;
}

// ---------------- h0 = relu(x @ Win + b) ------------------------------------
__global__ __launch_bounds__(256) void inproj_kernel(
    const float* __restrict__ x, const float* __restrict__ W,
    const float* __restrict__ b, float* __restrict__ hout) {
    __shared__ float sW[64 * 32];
    __shared__ float sb[32];
    int tid = threadIdx.x;
    for (int i = tid; i < 64 * 32; i += 256) sW[i] = W[i];
    if (tid < 32) sb[tid] = b[tid];
    __syncthreads();
    int lane = tid & 31, wid = tid >> 5;
    int n = blockIdx.x * 8 + wid;
    if (n >= N_NODES) return;
    float xa = x[n * 64 + lane];
    float xb = x[n * 64 + 32 + lane];
    float r = sb[lane];
#pragma unroll
    for (int k = 0; k < 32; k++)
        r = fmaf(__shfl_sync(0xffffffffu, xa, k), sW[k * 32 + lane], r);
#pragma unroll
    for (int k = 0; k < 32; k++)
        r = fmaf(__shfl_sync(0xffffffffu, xb, k), sW[(k + 32) * 32 + lane], r);
    hout[n * 32 + lane] = fmaxf(r, 0.f);
}

// ---------------- B fragment repack (all 3 layers, one launch) --------------
// g_w2f[((L*132 + t)*2 + ch)*32 + lane] = {bf16x2(v(col,kb),v(col,kb+1)),
//                                          bf16x2(v(col,kb+8),v(col,kb+9))}
// col = t*8 + (lane>>2); kb = ch*16 + (lane&3)*2.
// v(col,h): col<1024 -> w2[(col&31)*1024 + h*32 + (col>>5)]; else b2[h*32+col-1024]
__global__ __launch_bounds__(256) void w2f_kernel(
    const float* __restrict__ edge_w2, const float* __restrict__ edge_b2) {
    int idx = blockIdx.x * 256 + threadIdx.x;
    if (idx >= 3 * 132 * 2 * 32) return;
    int lane = idx & 31;
    int ch = (idx >> 5) & 1;
    int t = (idx >> 6) % 132;
    int L = idx / (132 * 64);
    const float* w2 = edge_w2 + L * 32768;
    const float* b2 = edge_b2 + L * 1024;
    int col = t * 8 + (lane >> 2);
    int kb = ch * 16 + (lane & 3) * 2;
    float v0, v1, v2, v3;
    if (col < 1024) {
        int o = col >> 5, k = col & 31;
        v0 = w2[k * 1024 + (kb + 0) * 32 + o];
        v1 = w2[k * 1024 + (kb + 1) * 32 + o];
        v2 = w2[k * 1024 + (kb + 8) * 32 + o];
        v3 = w2[k * 1024 + (kb + 9) * 32 + o];
    } else {
        int o = col - 1024;
        v0 = b2[(kb + 0) * 32 + o];
        v1 = b2[(kb + 1) * 32 + o];
        v2 = b2[(kb + 8) * 32 + o];
        v3 = b2[(kb + 9) * 32 + o];
    }
    __nv_bfloat162 p0 = __floats2bfloat162_rn(v0, v1);
    __nv_bfloat162 p1 = __floats2bfloat162_rn(v2, v3);
    uint2 w;
    w.x = *reinterpret_cast<unsigned*>(&p0);
    w.y = *reinterpret_cast<unsigned*>(&p1);
    g_w2f[idx] = w;
}

// ---------------- HMMA helper -----------------------------------------------
__device__ __forceinline__ void hmma16816(float* c, uint32_t a0, uint32_t a1,
                                          uint32_t a2, uint32_t a3,
                                          uint32_t b0, uint32_t b1) {
    asm volatile(
        "mma.sync.aligned.m16n8k16.row.col.f32.bf16.bf16.f32 "
        "{%0,%1,%2,%3}, {%4,%5,%6,%7}, {%8,%9}, {%0,%1,%2,%3};"
        : "+f"(c[0]), "+f"(c[1]), "+f"(c[2]), "+f"(c[3])
        : "r"(a0), "r"(a1), "r"(a2), "r"(a3), "r"(b0), "r"(b1));
}

// ---------------- fused layer: Y in smem + edge apply -----------------------
// Block = 16 source nodes. Phase 1: HMMA [16x32]@[32x1056] -> smem Y in
// [o][s][pair] layout (uint4-readable) + fp32 bias tile. Phase 2: bucketed
// edges read Y via LDS.128, he broadcast via smem, scatter to agg.
__global__ __launch_bounds__(256) void fused_layer_kernel(
    const float* __restrict__ h, const uint2* __restrict__ w2f,
    const float* __restrict__ ea, const float* __restrict__ w1,
    const float* __restrict__ b1, float* __restrict__ agg) {
    __shared__ __align__(16) unsigned sY[32 * Y_OSTR];   // 33.3 KB
    __shared__ float sBias[SB_NODES * 32];
    __shared__ __nv_bfloat16 sA[SB_NODES * 36];
    __shared__ float sw1[16 * 32];
    __shared__ float sb1[32];
    __shared__ __align__(16) float sHe[8 * 36];

    int tid = threadIdx.x, lane = tid & 31, wid = tid >> 5;
    int s0 = blockIdx.x * SB_NODES;

    for (int i = tid; i < 512; i += 256) {
        sw1[i] = w1[i];
        int r = i >> 5, k = i & 31;
        sA[r * 36 + k] = __float2bfloat16(__ldg(h + (size_t)(s0 + r) * 32 + k));
    }
    if (tid < 32) sb1[tid] = b1[tid];
    __syncthreads();

    // ---- Phase 1: MMA. All warps share the single m16 A-fragment.
    int r = lane >> 2;            // 0..7
    int kc = (lane & 3) * 2;
    uint32_t A0[2], A1[2], A2[2], A3[2];
#pragma unroll
    for (int ch = 0; ch < 2; ch++) {
        int kb = ch * 16 + kc;
        A0[ch] = *reinterpret_cast<const uint32_t*>(sA + r * 36 + kb);
        A1[ch] = *reinterpret_cast<const uint32_t*>(sA + (r + 8) * 36 + kb);
        A2[ch] = *reinterpret_cast<const uint32_t*>(sA + r * 36 + kb + 8);
        A3[ch] = *reinterpret_cast<const uint32_t*>(sA + (r + 8) * 36 + kb + 8);
    }

    for (int t = wid; t < 132; t += 8) {
        float c[4] = {0.f, 0.f, 0.f, 0.f};
#pragma unroll
        for (int ch = 0; ch < 2; ch++) {
            uint2 w = __ldg(w2f + (t * 2 + ch) * 32 + lane);
            hmma16816(c, A0[ch], A1[ch], A2[ch], A3[ch], w.x, w.y);
        }
        int col = t * 8 + kc;
        if (col < 1024) {
            int o = col >> 5, pr = (col & 31) >> 1;
            __nv_bfloat162 p0 = __floats2bfloat162_rn(c[0], c[1]);
            __nv_bfloat162 p1 = __floats2bfloat162_rn(c[2], c[3]);
            sY[o * Y_OSTR + r * 16 + pr] = *reinterpret_cast<unsigned*>(&p0);
            sY[o * Y_OSTR + (r + 8) * 16 + pr] = *reinterpret_cast<unsigned*>(&p1);
        } else {
            int o = col - 1024;
            *reinterpret_cast<float2*>(sBias + r * 32 + o) = make_float2(c[0], c[1]);
            *reinterpret_cast<float2*>(sBias + (r + 8) * 32 + o) = make_float2(c[2], c[3]);
        }
    }
    __syncthreads();

    // ---- Phase 2: this bucket's edges. lane = output o.
    float rw1[16];
#pragma unroll
    for (int j = 0; j < 16; j++) rw1[j] = sw1[j * 32 + lane];
    float rb1 = sb1[lane];
    float* whe = sHe + wid * 36;

    int cnt = min(g_bcnt[blockIdx.x], BCAP);
    const int* list = g_bkt + blockIdx.x * BCAP;
    for (int idx = wid; idx < cnt; idx += 8) {
        int e = list[idx];
        int s = g_src[e] - s0;
        int d = g_dst[e];

        const float4* eap = reinterpret_cast<const float4*>(ea + (size_t)e * 16);
        float acA = rb1, acB = 0.f;
#pragma unroll
        for (int j = 0; j < 2; j++) {
            float4 a0 = __ldg(eap + j);
            float4 a1 = __ldg(eap + j + 2);
            acA = fmaf(a0.x, rw1[4 * j + 0], acA);
            acB = fmaf(a1.x, rw1[4 * j + 8], acB);
            acA = fmaf(a0.y, rw1[4 * j + 1], acA);
            acB = fmaf(a1.y, rw1[4 * j + 9], acB);
            acA = fmaf(a0.z, rw1[4 * j + 2], acA);
            acB = fmaf(a1.z, rw1[4 * j + 10], acB);
            acA = fmaf(a0.w, rw1[4 * j + 3], acA);
            acB = fmaf(a1.w, rw1[4 * j + 11], acB);
        }
        float he = fmaxf(acA + acB, 0.f);
        whe[lane] = he;
        __syncwarp();

        const uint4* yb4 =
            reinterpret_cast<const uint4*>(sY + lane * Y_OSTR + s * 16);
        float m0 = sBias[s * 32 + lane], m1 = 0.f, m2 = 0.f, m3 = 0.f;
#pragma unroll
        for (int i = 0; i < 4; i++) {
            uint4 y = yb4[i];
            float4 h0 = *reinterpret_cast<const float4*>(whe + 8 * i);
            float4 h1 = *reinterpret_cast<const float4*>(whe + 8 * i + 4);
            m0 = fmaf(h0.x, __int_as_float(y.x << 16), m0);
            m1 = fmaf(h0.y, __int_as_float(y.x & 0xffff0000u), m1);
            m2 = fmaf(h0.z, __int_as_float(y.y << 16), m2);
            m3 = fmaf(h0.w, __int_as_float(y.y & 0xffff0000u), m3);
            m0 = fmaf(h1.x, __int_as_float(y.z << 16), m0);
            m1 = fmaf(h1.y, __int_as_float(y.z & 0xffff0000u), m1);
            m2 = fmaf(h1.z, __int_as_float(y.w << 16), m2);
            m3 = fmaf(h1.w, __int_as_float(y.w & 0xffff0000u), m3);
        }
        __syncwarp();
        atomicAdd(&agg[(size_t)d * 32 + lane], (m0 + m1) + (m2 + m3));
    }
}

// ---------------- node update (+ agg reset; + fused decoder on last) --------
__global__ __launch_bounds__(256) void node_update_kernel(
    const float* __restrict__ hin, float* __restrict__ agg,
    const float* __restrict__ cnt, const float* __restrict__ rW,
    const float* __restrict__ rb, float* __restrict__ hout, int last,
    const float* __restrict__ Wo, const float* __restrict__ bo,
    const float* __restrict__ W1, const float* __restrict__ b1d,
    const float* __restrict__ W2, const float* __restrict__ b2d,
    float* __restrict__ out) {
    __shared__ float sW[32 * 32];
    __shared__ float sb[32];
    __shared__ float sWo[32 * 16], sW1[16 * 32], sW2[32 * 64];
    __shared__ float sbo[16], sb1[32], sb2[64];
    int tid = threadIdx.x;
    for (int i = tid; i < 1024; i += 256) sW[i] = rW[i];
    if (tid < 32) sb[tid] = rb[tid];
    if (last) {
        for (int i = tid; i < 512; i += 256) { sWo[i] = Wo[i]; sW1[i] = W1[i]; }
        for (int i = tid; i < 2048; i += 256) sW2[i] = W2[i];
        if (tid < 16) sbo[tid] = bo[tid];
        if (tid < 32) sb1[tid] = b1d[tid];
        if (tid < 64) sb2[tid] = b2d[tid];
    }
    __syncthreads();
    int lane = tid & 31, wid = tid >> 5;
    int n = blockIdx.x * 8 + wid;
    if (n >= N_NODES) return;

    float a = agg[n * 32 + lane] / fmaxf(cnt[n], 1.f);
    float hv = hin[n * 32 + lane];
    float r = sb[lane] + a;
#pragma unroll
    for (int k = 0; k < 32; k++)
        r = fmaf(__shfl_sync(0xffffffffu, hv, k), sW[k * 32 + lane], r);
    float hnew = fmaxf(r, 0.f);

    if (!last) {
        agg[n * 32 + lane] = 0.f;   // reset for next layer's atomics
        hout[n * 32 + lane] = hnew;
        return;
    }

    int l16 = lane & 15;
    float z = sbo[l16];
#pragma unroll
    for (int k = 0; k < 32; k++)
        z = fmaf(__shfl_sync(0xffffffffu, hnew, k), sWo[k * 16 + l16], z);
    float d1 = sb1[lane];
#pragma unroll
    for (int j = 0; j < 16; j++)
        d1 = fmaf(__shfl_sync(0xffffffffu, z, j), sW1[j * 32 + lane], d1);
    d1 = fmaxf(d1, 0.f);
    float o0 = sb2[lane], o1 = sb2[32 + lane];
#pragma unroll
    for (int j = 0; j < 32; j++) {
        float dj = __shfl_sync(0xffffffffu, d1, j);
        o0 = fmaf(dj, sW2[j * 64 + lane], o0);
        o1 = fmaf(dj, sW2[j * 64 + 32 + lane], o1);
    }
    out[n * 64 + lane] = o0;
    out[n * 64 + 32 + lane] = o1;
}

// ---------------- launch ----------------
extern "C" void kernel_launch(void* const* d_in, const int* in_sizes, int n_in,
                              void* d_out, int out_size) {
    const float* x        = (const float*)d_in[0];
    const void*  ei       = d_in[1];
    const float* ea       = (const float*)d_in[2];
    const float* lin_in_w = (const float*)d_in[3];
    const float* lin_in_b = (const float*)d_in[4];
    const float* edge_w1  = (const float*)d_in[5];
    const float* edge_b1  = (const float*)d_in[6];
    const float* edge_w2  = (const float*)d_in[7];
    const float* edge_b2  = (const float*)d_in[8];
    const float* root_w   = (const float*)d_in[9];
    const float* root_b   = (const float*)d_in[10];
    const float* lout_w   = (const float*)d_in[11];
    const float* lout_b   = (const float*)d_in[12];
    const float* dec_w1   = (const float*)d_in[13];
    const float* dec_b1   = (const float*)d_in[14];
    const float* dec_w2   = (const float*)d_in[15];
    const float* dec_b2   = (const float*)d_in[16];
    float* out = (float*)d_out;

    void *p_agg, *p_cnt, *p_hA, *p_hB, *p_w2f, *p_bcnt;
    cudaGetSymbolAddress(&p_agg, g_agg);
    cudaGetSymbolAddress(&p_cnt, g_cnt);
    cudaGetSymbolAddress(&p_hA, g_hA);
    cudaGetSymbolAddress(&p_hB, g_hB);
    cudaGetSymbolAddress(&p_w2f, g_w2f);
    cudaGetSymbolAddress(&p_bcnt, g_bcnt);
    float* hbuf[4] = {(float*)p_hA, (float*)p_hB, (float*)p_hA, (float*)p_hB};

    cudaMemsetAsync(p_cnt, 0, (size_t)N_NODES * sizeof(float), 0);
    cudaMemsetAsync(p_agg, 0, (size_t)N_NODES * HID * sizeof(float), 0);
    cudaMemsetAsync(p_bcnt, 0, (size_t)NBKT * sizeof(int), 0);

    const int EB = (N_EDGES + 255) / 256;
    pre_kernel<<<EB, 256>>>(ei, (float*)p_cnt);
    w2f_kernel<<<(3 * 132 * 64 + 255) / 256, 256>>>(edge_w2, edge_b2);

    const int NB = (N_NODES + 7) / 8;
    inproj_kernel<<<NB, 256>>>(x, lin_in_w, lin_in_b, (float*)p_hA);

    for (int L = 0; L < 3; L++) {
        const float* w1 = edge_w1 + L * 16 * 32;
        const float* b1 = edge_b1 + L * 32;
        const float* rw = root_w + L * 32 * 32;
        const float* rb = root_b + L * 32;
        const float* hin = hbuf[L];
        float* hout = hbuf[L + 1];
        const uint2* w2fL = (const uint2*)p_w2f + (size_t)L * 132 * 64;

        fused_layer_kernel<<<NBKT, 256>>>(hin, w2fL, ea, w1, b1, (float*)p_agg);
        node_update_kernel<<<NB, 256>>>(hin, (float*)p_agg, (const float*)p_cnt,
                                        rw, rb, hout, (L == 2) ? 1 : 0,
                                        lout_w, lout_b, dec_w1, dec_b1,
                                        dec_w2, dec_b2, out);
    }
}

// round 17
// speedup vs baseline: 1.7496x; 1.0179x over previous
#include <cuda_runtime.h>
#include <cuda_bf16.h>
#include <stdint.h>

#define N_NODES 50000
#define N_EDGES 200000
#define HID 32
#define SB_NODES 16
#define NBKT 3125            // 50000 / 16 exactly
#define BCAP 512
#define Y_OSTR 260           // [o][s][pair] layout: o-stride in u32 (16*16 + 4 pad)

// ---------------- device scratch (static allocation only) ----------------
__device__ int   g_src[N_EDGES], g_dst[N_EDGES];
__device__ float g_hA[N_NODES * HID];
__device__ float g_hB[N_NODES * HID];
__device__ uint2 g_w2f[3 * 132 * 2 * 32];   // B fragments: [L][tile][chunk][lane]
__device__ float g_agg[N_NODES * HID];
__device__ float g_cnt[N_NODES];
__device__ int   g_bkt[NBKT * BCAP];
__device__ int   g_bcnt[NBKT];

// ---------------- fused pre: detect + normalize + dst counts + buckets ------
__global__ __launch_bounds__(256) void pre_kernel(const void* ei,
                                                  float* __restrict__ cnt) {
    __shared__ int any;
    if (threadIdx.x == 0) any = 0;
    __syncthreads();
    const unsigned* u = (const unsigned*)ei;
    int local = 0;
    for (int i = threadIdx.x; i < 2048; i += 256)
        if (u[2 * i + 1] != 0u) local = 1;
    if (local) atomicOr(&any, 1);
    __syncthreads();
    int is64 = (any == 0);

    int e = blockIdx.x * 256 + threadIdx.x;
    if (e >= N_EDGES) return;
    int s, d;
    if (is64) {
        const long long* p = (const long long*)ei;
        s = (int)p[e];
        d = (int)p[N_EDGES + e];
    } else {
        const int* p = (const int*)ei;
        s = p[e];
        d = p[N_EDGES + e];
    }
    s = min(max(s, 0), N_NODES - 1);
    d = min(max(d, 0), N_NODES - 1);
    g_src[e] = s;
    g_dst[e] = d;
    atomicAdd(&cnt[d], 1.f);
    int b = s >> 4;
    int p = atomicAdd(&g_bcnt[b], 1);
    if (p < BCAP) g_bkt[b * BCAP + p] = e;
}

// ---------------- h0 = relu(x @ Win + b): 4 nodes per warp, shfl-free -------
__global__ __launch_bounds__(256) void inproj_kernel(
    const float* __restrict__ x, const float* __restrict__ W,
    const float* __restrict__ b, float* __restrict__ hout) {
    __shared__ float sW[64 * 32];
    __shared__ float sb[32];
    int tid = threadIdx.x;
    for (int i = tid; i < 64 * 32; i += 256) sW[i] = W[i];
    if (tid < 32) sb[tid] = b[tid];
    __syncthreads();
    int lane = tid & 31, wid = tid >> 5;
    int n0 = blockIdx.x * 32 + wid * 4;
    int c0 = min(n0 + 0, N_NODES - 1);
    int c1 = min(n0 + 1, N_NODES - 1);
    int c2 = min(n0 + 2, N_NODES - 1);
    int c3 = min(n0 + 3, N_NODES - 1);
    float bb = sb[lane];
    float a0 = bb, a1 = bb, a2 = bb, a3 = bb;
#pragma unroll
    for (int kb = 0; kb < 16; kb++) {
        float4 x0 = __ldg((const float4*)(x + (size_t)c0 * 64) + kb);
        float4 x1 = __ldg((const float4*)(x + (size_t)c1 * 64) + kb);
        float4 x2 = __ldg((const float4*)(x + (size_t)c2 * 64) + kb);
        float4 x3 = __ldg((const float4*)(x + (size_t)c3 * 64) + kb);
        float w0 = sW[(kb * 4 + 0) * 32 + lane];
        float w1 = sW[(kb * 4 + 1) * 32 + lane];
        float w2 = sW[(kb * 4 + 2) * 32 + lane];
        float w3 = sW[(kb * 4 + 3) * 32 + lane];
        a0 = fmaf(x0.x, w0, a0); a1 = fmaf(x1.x, w0, a1);
        a2 = fmaf(x2.x, w0, a2); a3 = fmaf(x3.x, w0, a3);
        a0 = fmaf(x0.y, w1, a0); a1 = fmaf(x1.y, w1, a1);
        a2 = fmaf(x2.y, w1, a2); a3 = fmaf(x3.y, w1, a3);
        a0 = fmaf(x0.z, w2, a0); a1 = fmaf(x1.z, w2, a1);
        a2 = fmaf(x2.z, w2, a2); a3 = fmaf(x3.z, w2, a3);
        a0 = fmaf(x0.w, w3, a0); a1 = fmaf(x1.w, w3, a1);
        a2 = fmaf(x2.w, w3, a2); a3 = fmaf(x3.w, w3, a3);
    }
    if (n0 + 0 < N_NODES) hout[(size_t)(n0 + 0) * 32 + lane] = fmaxf(a0, 0.f);
    if (n0 + 1 < N_NODES) hout[(size_t)(n0 + 1) * 32 + lane] = fmaxf(a1, 0.f);
    if (n0 + 2 < N_NODES) hout[(size_t)(n0 + 2) * 32 + lane] = fmaxf(a2, 0.f);
    if (n0 + 3 < N_NODES) hout[(size_t)(n0 + 3) * 32 + lane] = fmaxf(a3, 0.f);
}

// ---------------- B fragment repack (all 3 layers, one launch) --------------
__global__ __launch_bounds__(256) void w2f_kernel(
    const float* __restrict__ edge_w2, const float* __restrict__ edge_b2) {
    int idx = blockIdx.x * 256 + threadIdx.x;
    if (idx >= 3 * 132 * 2 * 32) return;
    int lane = idx & 31;
    int ch = (idx >> 5) & 1;
    int t = (idx >> 6) % 132;
    int L = idx / (132 * 64);
    const float* w2 = edge_w2 + L * 32768;
    const float* b2 = edge_b2 + L * 1024;
    int col = t * 8 + (lane >> 2);
    int kb = ch * 16 + (lane & 3) * 2;
    float v0, v1, v2, v3;
    if (col < 1024) {
        int o = col >> 5, k = col & 31;
        v0 = w2[k * 1024 + (kb + 0) * 32 + o];
        v1 = w2[k * 1024 + (kb + 1) * 32 + o];
        v2 = w2[k * 1024 + (kb + 8) * 32 + o];
        v3 = w2[k * 1024 + (kb + 9) * 32 + o];
    } else {
        int o = col - 1024;
        v0 = b2[(kb + 0) * 32 + o];
        v1 = b2[(kb + 1) * 32 + o];
        v2 = b2[(kb + 8) * 32 + o];
        v3 = b2[(kb + 9) * 32 + o];
    }
    __nv_bfloat162 p0 = __floats2bfloat162_rn(v0, v1);
    __nv_bfloat162 p1 = __floats2bfloat162_rn(v2, v3);
    uint2 w;
    w.x = *reinterpret_cast<unsigned*>(&p0);
    w.y = *reinterpret_cast<unsigned*>(&p1);
    g_w2f[idx] = w;
}

// ---------------- HMMA helper -----------------------------------------------
__device__ __forceinline__ void hmma16816(float* c, uint32_t a0, uint32_t a1,
                                          uint32_t a2, uint32_t a3,
                                          uint32_t b0, uint32_t b1) {
    asm volatile(
        "mma.sync.aligned.m16n8k16.row.col.f32.bf16.bf16.f32 "
        "{%0,%1,%2,%3}, {%4,%5,%6,%7}, {%8,%9}, {%0,%1,%2,%3};"
        : "+f"(c[0]), "+f"(c[1]), "+f"(c[2]), "+f"(c[3])
        : "r"(a0), "r"(a1), "r"(a2), "r"(a3), "r"(b0), "r"(b1));
}

// ---------------- fused layer: Y in smem + dual-edge apply ------------------
__global__ __launch_bounds__(256) void fused_layer_kernel(
    const float* __restrict__ h, const uint2* __restrict__ w2f,
    const float* __restrict__ ea, const float* __restrict__ w1,
    const float* __restrict__ b1, float* __restrict__ agg) {
    __shared__ __align__(16) unsigned sY[32 * Y_OSTR];   // 33.3 KB
    __shared__ float sBias[SB_NODES * 32];
    __shared__ __nv_bfloat16 sA[SB_NODES * 36];
    __shared__ float sw1[16 * 32];
    __shared__ float sb1[32];
    __shared__ __align__(16) float sHe[8 * 72];          // 2 rows of 36 per warp

    int tid = threadIdx.x, lane = tid & 31, wid = tid >> 5;
    int s0 = blockIdx.x * SB_NODES;

    for (int i = tid; i < 512; i += 256) {
        sw1[i] = w1[i];
        int r = i >> 5, k = i & 31;
        sA[r * 36 + k] = __float2bfloat16(__ldg(h + (size_t)(s0 + r) * 32 + k));
    }
    if (tid < 32) sb1[tid] = b1[tid];
    __syncthreads();

    // ---- Phase 1: MMA. All warps share the single m16 A-fragment.
    int r = lane >> 2;            // 0..7
    int kc = (lane & 3) * 2;
    uint32_t A0[2], A1[2], A2[2], A3[2];
#pragma unroll
    for (int ch = 0; ch < 2; ch++) {
        int kb = ch * 16 + kc;
        A0[ch] = *reinterpret_cast<const uint32_t*>(sA + r * 36 + kb);
        A1[ch] = *reinterpret_cast<const uint32_t*>(sA + (r + 8) * 36 + kb);
        A2[ch] = *reinterpret_cast<const uint32_t*>(sA + r * 36 + kb + 8);
        A3[ch] = *reinterpret_cast<const uint32_t*>(sA + (r + 8) * 36 + kb + 8);
    }

    for (int t = wid; t < 132; t += 8) {
        float c[4] = {0.f, 0.f, 0.f, 0.f};
#pragma unroll
        for (int ch = 0; ch < 2; ch++) {
            uint2 w = __ldg(w2f + (t * 2 + ch) * 32 + lane);
            hmma16816(c, A0[ch], A1[ch], A2[ch], A3[ch], w.x, w.y);
        }
        int col = t * 8 + kc;
        if (col < 1024) {
            int o = col >> 5, pr = (col & 31) >> 1;
            __nv_bfloat162 p0 = __floats2bfloat162_rn(c[0], c[1]);
            __nv_bfloat162 p1 = __floats2bfloat162_rn(c[2], c[3]);
            sY[o * Y_OSTR + r * 16 + pr] = *reinterpret_cast<unsigned*>(&p0);
            sY[o * Y_OSTR + (r + 8) * 16 + pr] = *reinterpret_cast<unsigned*>(&p1);
        } else {
            int o = col - 1024;
            *reinterpret_cast<float2*>(sBias + r * 32 + o) = make_float2(c[0], c[1]);
            *reinterpret_cast<float2*>(sBias + (r + 8) * 32 + o) = make_float2(c[2], c[3]);
        }
    }
    __syncthreads();

    // ---- Phase 2: dual-edge per iteration. lane = output o.
    float rw1[16];
#pragma unroll
    for (int j = 0; j < 16; j++) rw1[j] = sw1[j * 32 + lane];
    float rb1 = sb1[lane];
    float* whe = sHe + wid * 72;

    int cnt = min(g_bcnt[blockIdx.x], BCAP);
    const int* list = g_bkt + blockIdx.x * BCAP;
    for (int idx = wid * 2; idx < cnt; idx += 16) {
        int e0 = list[idx];
        bool has1 = (idx + 1 < cnt);
        int e1 = has1 ? list[idx + 1] : e0;
        int sA0 = g_src[e0] - s0, dA0 = g_dst[e0];
        int sA1 = g_src[e1] - s0, dA1 = g_dst[e1];

        const float4* p0 = reinterpret_cast<const float4*>(ea + (size_t)e0 * 16);
        const float4* p1 = reinterpret_cast<const float4*>(ea + (size_t)e1 * 16);
        float x0 = rb1, y0 = 0.f, x1 = rb1, y1 = 0.f;
#pragma unroll
        for (int j = 0; j < 2; j++) {
            float4 a0 = __ldg(p0 + j);
            float4 b0 = __ldg(p0 + j + 2);
            float4 a1 = __ldg(p1 + j);
            float4 b1v = __ldg(p1 + j + 2);
            x0 = fmaf(a0.x, rw1[4 * j + 0], x0);  y0 = fmaf(b0.x, rw1[4 * j + 8], y0);
            x1 = fmaf(a1.x, rw1[4 * j + 0], x1);  y1 = fmaf(b1v.x, rw1[4 * j + 8], y1);
            x0 = fmaf(a0.y, rw1[4 * j + 1], x0);  y0 = fmaf(b0.y, rw1[4 * j + 9], y0);
            x1 = fmaf(a1.y, rw1[4 * j + 1], x1);  y1 = fmaf(b1v.y, rw1[4 * j + 9], y1);
            x0 = fmaf(a0.z, rw1[4 * j + 2], x0);  y0 = fmaf(b0.z, rw1[4 * j + 10], y0);
            x1 = fmaf(a1.z, rw1[4 * j + 2], x1);  y1 = fmaf(b1v.z, rw1[4 * j + 10], y1);
            x0 = fmaf(a0.w, rw1[4 * j + 3], x0);  y0 = fmaf(b0.w, rw1[4 * j + 11], y0);
            x1 = fmaf(a1.w, rw1[4 * j + 3], x1);  y1 = fmaf(b1v.w, rw1[4 * j + 11], y1);
        }
        whe[lane] = fmaxf(x0 + y0, 0.f);
        whe[36 + lane] = fmaxf(x1 + y1, 0.f);
        __syncwarp();

        {   // edge 0 dot
            const uint4* yb4 =
                reinterpret_cast<const uint4*>(sY + lane * Y_OSTR + sA0 * 16);
            float m0 = sBias[sA0 * 32 + lane], m1 = 0.f, m2 = 0.f, m3 = 0.f;
#pragma unroll
            for (int i = 0; i < 4; i++) {
                uint4 y = yb4[i];
                float4 h0 = *reinterpret_cast<const float4*>(whe + 8 * i);
                float4 h1 = *reinterpret_cast<const float4*>(whe + 8 * i + 4);
                m0 = fmaf(h0.x, __int_as_float(y.x << 16), m0);
                m1 = fmaf(h0.y, __int_as_float(y.x & 0xffff0000u), m1);
                m2 = fmaf(h0.z, __int_as_float(y.y << 16), m2);
                m3 = fmaf(h0.w, __int_as_float(y.y & 0xffff0000u), m3);
                m0 = fmaf(h1.x, __int_as_float(y.z << 16), m0);
                m1 = fmaf(h1.y, __int_as_float(y.z & 0xffff0000u), m1);
                m2 = fmaf(h1.z, __int_as_float(y.w << 16), m2);
                m3 = fmaf(h1.w, __int_as_float(y.w & 0xffff0000u), m3);
            }
            atomicAdd(&agg[(size_t)dA0 * 32 + lane], (m0 + m1) + (m2 + m3));
        }
        if (has1) {   // edge 1 dot
            const uint4* yb4 =
                reinterpret_cast<const uint4*>(sY + lane * Y_OSTR + sA1 * 16);
            float m0 = sBias[sA1 * 32 + lane], m1 = 0.f, m2 = 0.f, m3 = 0.f;
#pragma unroll
            for (int i = 0; i < 4; i++) {
                uint4 y = yb4[i];
                float4 h0 = *reinterpret_cast<const float4*>(whe + 36 + 8 * i);
                float4 h1 = *reinterpret_cast<const float4*>(whe + 36 + 8 * i + 4);
                m0 = fmaf(h0.x, __int_as_float(y.x << 16), m0);
                m1 = fmaf(h0.y, __int_as_float(y.x & 0xffff0000u), m1);
                m2 = fmaf(h0.z, __int_as_float(y.y << 16), m2);
                m3 = fmaf(h0.w, __int_as_float(y.y & 0xffff0000u), m3);
                m0 = fmaf(h1.x, __int_as_float(y.z << 16), m0);
                m1 = fmaf(h1.y, __int_as_float(y.z & 0xffff0000u), m1);
                m2 = fmaf(h1.z, __int_as_float(y.w << 16), m2);
                m3 = fmaf(h1.w, __int_as_float(y.w & 0xffff0000u), m3);
            }
            atomicAdd(&agg[(size_t)dA1 * 32 + lane], (m0 + m1) + (m2 + m3));
        }
        __syncwarp();
    }
}

// ---------------- node update (+ agg reset; + fused decoder on last) --------
__global__ __launch_bounds__(256) void node_update_kernel(
    const float* __restrict__ hin, float* __restrict__ agg,
    const float* __restrict__ cnt, const float* __restrict__ rW,
    const float* __restrict__ rb, float* __restrict__ hout, int last,
    const float* __restrict__ Wo, const float* __restrict__ bo,
    const float* __restrict__ W1, const float* __restrict__ b1d,
    const float* __restrict__ W2, const float* __restrict__ b2d,
    float* __restrict__ out) {
    __shared__ float sW[32 * 32];
    __shared__ float sb[32];
    __shared__ float sWo[32 * 16], sW1[16 * 32], sW2[32 * 64];
    __shared__ float sbo[16], sb1[32], sb2[64];
    int tid = threadIdx.x;
    for (int i = tid; i < 1024; i += 256) sW[i] = rW[i];
    if (tid < 32) sb[tid] = rb[tid];
    if (last) {
        for (int i = tid; i < 512; i += 256) { sWo[i] = Wo[i]; sW1[i] = W1[i]; }
        for (int i = tid; i < 2048; i += 256) sW2[i] = W2[i];
        if (tid < 16) sbo[tid] = bo[tid];
        if (tid < 32) sb1[tid] = b1d[tid];
        if (tid < 64) sb2[tid] = b2d[tid];
    }
    __syncthreads();
    int lane = tid & 31, wid = tid >> 5;
    int n = blockIdx.x * 8 + wid;
    if (n >= N_NODES) return;

    float a = agg[n * 32 + lane] / fmaxf(cnt[n], 1.f);
    float r = sb[lane] + a;
    const float4* hp = reinterpret_cast<const float4*>(hin + (size_t)n * 32);
#pragma unroll
    for (int kb = 0; kb < 8; kb++) {
        float4 hq = __ldg(hp + kb);
        r = fmaf(hq.x, sW[(kb * 4 + 0) * 32 + lane], r);
        r = fmaf(hq.y, sW[(kb * 4 + 1) * 32 + lane], r);
        r = fmaf(hq.z, sW[(kb * 4 + 2) * 32 + lane], r);
        r = fmaf(hq.w, sW[(kb * 4 + 3) * 32 + lane], r);
    }
    float hnew = fmaxf(r, 0.f);

    if (!last) {
        agg[n * 32 + lane] = 0.f;   // reset for next layer's atomics
        hout[n * 32 + lane] = hnew;
        return;
    }

    int l16 = lane & 15;
    float z = sbo[l16];
#pragma unroll
    for (int k = 0; k < 32; k++)
        z = fmaf(__shfl_sync(0xffffffffu, hnew, k), sWo[k * 16 + l16], z);
    float d1 = sb1[lane];
#pragma unroll
    for (int j = 0; j < 16; j++)
        d1 = fmaf(__shfl_sync(0xffffffffu, z, j), sW1[j * 32 + lane], d1);
    d1 = fmaxf(d1, 0.f);
    float o0 = sb2[lane], o1 = sb2[32 + lane];
#pragma unroll
    for (int j = 0; j < 32; j++) {
        float dj = __shfl_sync(0xffffffffu, d1, j);
        o0 = fmaf(dj, sW2[j * 64 + lane], o0);
        o1 = fmaf(dj, sW2[j * 64 + 32 + lane], o1);
    }
    out[n * 64 + lane] = o0;
    out[n * 64 + 32 + lane] = o1;
}

// ---------------- launch ----------------
extern "C" void kernel_launch(void* const* d_in, const int* in_sizes, int n_in,
                              void* d_out, int out_size) {
    const float* x        = (const float*)d_in[0];
    const void*  ei       = d_in[1];
    const float* ea       = (const float*)d_in[2];
    const float* lin_in_w = (const float*)d_in[3];
    const float* lin_in_b = (const float*)d_in[4];
    const float* edge_w1  = (const float*)d_in[5];
    const float* edge_b1  = (const float*)d_in[6];
    const float* edge_w2  = (const float*)d_in[7];
    const float* edge_b2  = (const float*)d_in[8];
    const float* root_w   = (const float*)d_in[9];
    const float* root_b   = (const float*)d_in[10];
    const float* lout_w   = (const float*)d_in[11];
    const float* lout_b   = (const float*)d_in[12];
    const float* dec_w1   = (const float*)d_in[13];
    const float* dec_b1   = (const float*)d_in[14];
    const float* dec_w2   = (const float*)d_in[15];
    const float* dec_b2   = (const float*)d_in[16];
    float* out = (float*)d_out;

    void *p_agg, *p_cnt, *p_hA, *p_hB, *p_w2f, *p_bcnt;
    cudaGetSymbolAddress(&p_agg, g_agg);
    cudaGetSymbolAddress(&p_cnt, g_cnt);
    cudaGetSymbolAddress(&p_hA, g_hA);
    cudaGetSymbolAddress(&p_hB, g_hB);
    cudaGetSymbolAddress(&p_w2f, g_w2f);
    cudaGetSymbolAddress(&p_bcnt, g_bcnt);
    float* hbuf[4] = {(float*)p_hA, (float*)p_hB, (float*)p_hA, (float*)p_hB};

    cudaMemsetAsync(p_cnt, 0, (size_t)N_NODES * sizeof(float), 0);
    cudaMemsetAsync(p_agg, 0, (size_t)N_NODES * HID * sizeof(float), 0);
    cudaMemsetAsync(p_bcnt, 0, (size_t)NBKT * sizeof(int), 0);

    const int EB = (N_EDGES + 255) / 256;
    pre_kernel<<<EB, 256>>>(ei, (float*)p_cnt);
    w2f_kernel<<<(3 * 132 * 64 + 255) / 256, 256>>>(edge_w2, edge_b2);

    inproj_kernel<<<(N_NODES + 31) / 32, 256>>>(x, lin_in_w, lin_in_b,
                                                (float*)p_hA);

    const int NB = (N_NODES + 7) / 8;
    for (int L = 0; L < 3; L++) {
        const float* w1 = edge_w1 + L * 16 * 32;
        const float* b1 = edge_b1 + L * 32;
        const float* rw = root_w + L * 32 * 32;
        const float* rb = root_b + L * 32;
        const float* hin = hbuf[L];
        float* hout = hbuf[L + 1];
        const uint2* w2fL = (const uint2*)p_w2f + (size_t)L * 132 * 64;

        fused_layer_kernel<<<NBKT, 256>>>(hin, w2fL, ea, w1, b1, (float*)p_agg);
        node_update_kernel<<<NB, 256>>>(hin, (float*)p_agg, (const float*)p_cnt,
                                        rw, rb, hout, (L == 2) ? 1 : 0,
                                        lout_w, lout_b, dec_w1, dec_b1,
                                        dec_w2, dec_b2, out);
    }
}